// round 3
// baseline (speedup 1.0000x reference)
#include <cuda_runtime.h>
#include <cstdint>

// Problem constants (match reference)
#define N_EVENTS   16
#define N_SAMPLES  32768
#define STEP_SIZE  256
#define BATCH      64

// 128 threads/CTA. Each thread produces TWO float4 groups: one in the lower
// half of the output, one mirrored in the upper half. Coverage(j) grows
// ~linearly in j, so coverage(j_lo)+coverage(j_hi) ~ constant -> every CTA
// does (nearly) the same amount of DRAM traffic. 2048 equal CTAs / 148 SMs
// amortizes the tail to ~7%.
#define THREADS    128
#define HALF_CHUNK (THREADS * 4)          // 512 samples
#define CHUNKS     (N_SAMPLES / 2 / HALF_CHUNK)  // 32

__global__ __launch_bounds__(THREADS)
void render_gather_kernel(const float* __restrict__ x,
                          const int* __restrict__ indices,
                          float* __restrict__ out) {
    const int b  = blockIdx.y;
    const int bx = blockIdx.x;                       // [0, 32)
    const int j1 = bx * HALF_CHUNK + threadIdx.x * 4;                    // [0, 16384)
    const int j2 = N_SAMPLES - HALF_CHUNK * (bx + 1) + threadIdx.x * 4;  // [16384, 32768)

    // Broadcast the 16 event start-times for this batch into shared memory.
    __shared__ int t_start[N_EVENTS];
    if (threadIdx.x < N_EVENTS) {
        t_start[threadIdx.x] = indices[b * N_EVENTS + threadIdx.x] * STEP_SIZE;
    }
    __syncthreads();

    const float* xb = x + (size_t)b * N_EVENTS * N_SAMPLES;

    float4 acc1 = make_float4(0.f, 0.f, 0.f, 0.f);
    float4 acc2 = make_float4(0.f, 0.f, 0.f, 0.f);

    #pragma unroll
    for (int e = 0; e < N_EVENTS; e++) {
        const int t = t_start[e];
        const float* xe = xb + (size_t)e * N_SAMPLES;
        // t multiple of 256, j multiple of 4 -> offsets stay 16B aligned.
        // j - t < N_SAMPLES always holds (j < N_SAMPLES, t >= 0).
        if (j1 >= t) {
            const float4 v = __ldcs(reinterpret_cast<const float4*>(xe + (j1 - t)));
            acc1.x += v.x; acc1.y += v.y; acc1.z += v.z; acc1.w += v.w;
        }
        if (j2 >= t) {
            const float4 v = __ldcs(reinterpret_cast<const float4*>(xe + (j2 - t)));
            acc2.x += v.x; acc2.y += v.y; acc2.z += v.z; acc2.w += v.w;
        }
    }

    float* ob = out + (size_t)b * N_SAMPLES;
    __stcs(reinterpret_cast<float4*>(ob + j1), acc1);
    __stcs(reinterpret_cast<float4*>(ob + j2), acc2);
}

extern "C" void kernel_launch(void* const* d_in, const int* in_sizes, int n_in,
                              void* d_out, int out_size) {
    const float* x = (const float*)d_in[0];          // (64, 16, 32768) f32
    const int* indices = (const int*)d_in[1];        // (64, 16) int32
    float* out = (float*)d_out;                      // (64, 1, 32768) f32

    dim3 grid(CHUNKS, BATCH);                        // (32, 64) = 2048 CTAs
    render_gather_kernel<<<grid, THREADS>>>(x, indices, out);
}